// round 7
// baseline (speedup 1.0000x reference)
#include <cuda_runtime.h>
#include <cuda_bf16.h>
#include <math.h>

// CropRoi: f (B=4, C=64, 32,32,32) f32; proposals (N,8) [b,score,cx,cy,cz,sx,sy,sz]
// out (N,C,7,7,7) f32. dims_max=32, R=7.
// Derived invariants: L = c1-c0 in [2,13]  =>  every bin window width in [1,3].

#define R_BINS 7
#define C_CH   64
#define DIMMAX 32
#define NW     11      // warps per block
#define NTHREADS 352
#define MAXL   14      // wp pitch (L <= 13)

__global__ __launch_bounds__(NTHREADS) void crop_roi_kernel(
        const float* __restrict__ f,
        const float* __restrict__ props,
        float* __restrict__ out) {
    const int n   = blockIdx.x;
    const int c   = blockIdx.y;
    const int tid = threadIdx.x;
    const int lane = tid & 31;
    const int warp = tid >> 5;

    __shared__ int sS[3][R_BINS], sE[3][R_BINS];
    __shared__ int sC0[2], sL[2], sB;
    __shared__ float wp[MAXL * MAXL * 8];   // w-pooled rows: [dd][hh][7(+pad)]

    // ---- bounds (21 threads) ----
    if (tid < 3 * R_BINS) {
        const int ax = tid / R_BINS;               // const-div, magic-mul
        const int bi = tid - ax * R_BINS;
        const float* p = props + (size_t)n * 8;
        if (tid == 0) sB = (int)p[0];
        float center = __ldg(p + 2 + ax);
        float side   = __ldg(p + 5 + ax);
        // *0.5f / *0.25f are exact (powers of two) -> bitwise-matches jnp
        int c0 = (int)floorf((center - 0.5f * side) * 0.25f);
        int c1 = (int)ceilf ((center + 0.5f * side) * 0.25f);
        c0 = max(c0, 0);
        c1 = min(c1, DIMMAX);
        int L  = c1 - c0;
        int ss = c0 + (bi * L) / R_BINS;                     // floor div
        int ee = c0 + ((bi + 1) * L + R_BINS - 1) / R_BINS;  // ceil div
        ee = min(ee, ss + 6);                                // K cap (never binds; safety)
        sS[ax][bi] = ss;
        sE[ax][bi] = ee;
        if (bi == 0 && ax < 2) { sC0[ax] = c0; sL[ax] = L; }
    }
    __syncthreads();

    const int c0d = sC0[0], c0h = sC0[1];
    const int Ld  = sL[0],  Lh  = sL[1];
    const int nrows = Ld * Lh;
    const float* base = f + (((size_t)sB * C_CH + c) << 15);  // 32^3 floats per (b,c)

    // hoisted per-lane w-bin shuffle indices (clamp-duplicate, max-idempotent)
    const int kl = (lane < R_BINS) ? lane : 0;
    const int ws = sS[2][kl];
    const int wl = sE[2][kl] - 1;
    const int m0 = ws;
    const int m1 = min(ws + 1, wl);
    const int m2 = min(ws + 2, wl);

    // magic divide by dynamic Lh (exact for r<196, Lh<=13)
    const unsigned M = (1u << 20) / (unsigned)Lh + 1u;

    // ---- phase 1: coalesced row loads + shuffle w-pool ----
    for (int r = warp; r < nrows; r += NW) {
        int dd = (int)(((unsigned)r * M) >> 20);
        int hh = r - dd * Lh;
        const float* row = base + ((c0d + dd) << 10) + ((c0h + hh) << 5);
        float v = row[lane];                       // one 128B coalesced LDG per row
        float a  = __shfl_sync(0xffffffffu, v, m0);
        float b  = __shfl_sync(0xffffffffu, v, m1);
        float c2 = __shfl_sync(0xffffffffu, v, m2);
        float mx = fmaxf(a, fmaxf(b, c2));
        if (lane < R_BINS)
            wp[(dd * MAXL + hh) * 8 + lane] = mx;
    }
    __syncthreads();

    // ---- phase 2: 3x3 clamp-duplicated d/h pool from smem ----
    if (tid < 343) {
        int i   = tid / 49;          // const-div
        int rem = tid - i * 49;
        int j   = rem / 7;
        int k   = rem - j * 7;

        int ds = sS[0][i] - c0d, dl = sE[0][i] - 1 - c0d;
        int hs = sS[1][j] - c0h, hl = sE[1][j] - 1 - c0h;
        int d0 = ds, d1 = min(ds + 1, dl), d2 = min(ds + 2, dl);
        int h0 = hs, h1 = min(hs + 1, hl), h2 = min(hs + 2, hl);

        const float* w0 = wp + k;
        float m =          w0[(d0 * MAXL + h0) * 8];
        m = fmaxf(m,       w0[(d0 * MAXL + h1) * 8]);
        m = fmaxf(m,       w0[(d0 * MAXL + h2) * 8]);
        m = fmaxf(m,       w0[(d1 * MAXL + h0) * 8]);
        m = fmaxf(m,       w0[(d1 * MAXL + h1) * 8]);
        m = fmaxf(m,       w0[(d1 * MAXL + h2) * 8]);
        m = fmaxf(m,       w0[(d2 * MAXL + h0) * 8]);
        m = fmaxf(m,       w0[(d2 * MAXL + h1) * 8]);
        m = fmaxf(m,       w0[(d2 * MAXL + h2) * 8]);

        out[((size_t)n * C_CH + c) * 343 + tid] = m;
    }
}

extern "C" void kernel_launch(void* const* d_in, const int* in_sizes, int n_in,
                              void* d_out, int out_size) {
    const float* f     = (const float*)d_in[0];
    const float* props = (const float*)d_in[2];
    float* out = (float*)d_out;

    int n_props = in_sizes[2] / 8;
    dim3 grid(n_props, C_CH);
    crop_roi_kernel<<<grid, NTHREADS>>>(f, props, out);
}

// round 8
// speedup vs baseline: 1.6514x; 1.6514x over previous
#include <cuda_runtime.h>
#include <cuda_bf16.h>
#include <math.h>

// CropRoi: f (B=4, C=64, 32,32,32) f32; proposals (N,8) [b,score,cx,cy,cz,sx,sy,sz]
// out (N,C,7,7,7) f32. dims_max=32, R=7. L = c1-c0 in [2,13] => bin widths in [1,3].
//
// Strategy: block = (proposal n, channel-group of CG). All channels share bin
// bounds, so each thread computes its bin's gather ONCE and accumulates CG
// channels via fixed-immediate-offset loads (amortizes all addressing 4x).

#define R_BINS 7
#define C_CH   64
#define DIMMAX 32
#define CG     4            // channels per thread
#define NTHREADS 352
#define CHSTRIDE 32768      // floats per (b,c) volume: 32^3

__global__ __launch_bounds__(NTHREADS, 5) void crop_roi_kernel(
        const float* __restrict__ f,
        const float* __restrict__ props,
        float* __restrict__ out) {
    const int n  = blockIdx.x;
    const int cb = blockIdx.y * CG;     // first channel of this group
    const int tid = threadIdx.x;

    __shared__ int sS[3][R_BINS], sE[3][R_BINS];
    __shared__ int sB;

    // ---- bounds (21 threads), bitwise-identical to reference math ----
    if (tid < 3 * R_BINS) {
        const int ax = tid / R_BINS;
        const int bi = tid - ax * R_BINS;
        const float* p = props + (size_t)n * 8;
        if (tid == 0) sB = (int)p[0];
        float center = __ldg(p + 2 + ax);
        float side   = __ldg(p + 5 + ax);
        // *0.5f and *0.25f exact (powers of two) -> matches jnp arithmetic
        int c0 = (int)floorf((center - 0.5f * side) * 0.25f);
        int c1 = (int)ceilf ((center + 0.5f * side) * 0.25f);
        c0 = max(c0, 0);
        c1 = min(c1, DIMMAX);
        int L  = c1 - c0;
        int ss = c0 + (bi * L) / R_BINS;                     // floor div
        int ee = c0 + ((bi + 1) * L + R_BINS - 1) / R_BINS;  // ceil div
        ee = min(ee, ss + 6);                                // K cap (safety)
        sS[ax][bi] = ss;
        sE[ax][bi] = ee;
    }
    __syncthreads();

    if (tid >= 343) return;

    const int i   = tid / 49;
    const int rem = tid - i * 49;
    const int j   = rem / 7;
    const int k   = rem - j * 7;

    const int sd = sS[0][i], ed = sE[0][i];
    const int sh = sS[1][j], eh = sE[1][j];
    const int sw = sS[2][k], ew = sE[2][k];

    const float* base = f + (((size_t)sB * C_CH + cb) << 15);

    float m0 = -3.402823466e+38f;   // finfo(float32).min
    float m1 = m0, m2 = m0, m3 = m0;

    for (int d = sd; d < ed; d++) {
        const float* pd = base + (d << 10);
        for (int h = sh; h < eh; h++) {
            const float* p = pd + (h << 5) + sw;
            for (int w = sw; w < ew; w++, p++) {
                // fixed byte offsets k*131072 -> encoded in LDG immediates
                m0 = fmaxf(m0, p[0 * CHSTRIDE]);
                m1 = fmaxf(m1, p[1 * CHSTRIDE]);
                m2 = fmaxf(m2, p[2 * CHSTRIDE]);
                m3 = fmaxf(m3, p[3 * CHSTRIDE]);
            }
        }
    }

    size_t o = ((size_t)n * C_CH + cb) * 343 + tid;
    out[o]           = m0;
    out[o + 343]     = m1;
    out[o + 2 * 343] = m2;
    out[o + 3 * 343] = m3;
}

extern "C" void kernel_launch(void* const* d_in, const int* in_sizes, int n_in,
                              void* d_out, int out_size) {
    const float* f     = (const float*)d_in[0];
    const float* props = (const float*)d_in[2];
    float* out = (float*)d_out;

    int n_props = in_sizes[2] / 8;
    dim3 grid(n_props, C_CH / CG);
    crop_roi_kernel<<<grid, NTHREADS>>>(f, props, out);
}